// round 4
// baseline (speedup 1.0000x reference)
#include <cuda_runtime.h>
#include <cuda_bf16.h>
#include <math.h>

// Problem constants
#define B_      16
#define T_      4
#define D_      2048
#define H_      8
#define G_      4
#define GSZ_    2
#define HD_     256
#define BLOCK_  16
#define WINDOW_ 1024
#define NBLK_   257
#define NCHUNK  4
#define NQ      8            // GSZ_ * T_ queries per (b,g)
#define SCALE_  0.0625f      // 256^-0.5
#define EPS_    1e-6f

// -------- device scratch (no allocs allowed) --------
__device__ __align__(16) float g_q [B_*T_*H_*HD_];          // 131072
__device__ __align__(16) float g_k [B_*T_*G_*HD_];          // 65536
__device__ __align__(16) float g_v [B_*T_*G_*HD_];          // 65536
__device__ __align__(16) float g_o [B_*T_*H_*HD_];          // 131072
__device__ __align__(16) float g_po[B_*G_*NCHUNK*NQ*HD_];   // 524288
__device__ __align__(16) float g_pm[B_*G_*NCHUNK*NQ];
__device__ __align__(16) float g_pl[B_*G_*NCHUNK*NQ];

// -------- zero scratch + output (atomic accumulation targets) --------
__global__ void zero_kernel(float* __restrict__ out) {
    int i = blockIdx.x * 256 + threadIdx.x;   // grid 512 -> i < 131072
    if (i < B_*T_*H_*HD_) g_q[i] = 0.f;
    if (i < B_*T_*G_*HD_) { g_k[i] = 0.f; g_v[i] = 0.f; }
    if (i < B_*T_*D_)     out[i] = 0.f;
}

// -------- GEMM  C[64,N] += A[64,K] * B[N,K]^T  (both K-contiguous) --------
// BM=64 (full M), BN=64, BK=16, 256 threads, 4x4 microtile, split-K via atomics.
// DST: 0->g_q, 1->g_k, 2->g_v, 3->Cext with A taken from g_o (device symbol,
// must NOT be passed from host!).
template<int DST>
__global__ __launch_bounds__(256)
void gemm_nt(const float* __restrict__ Ain, const float* __restrict__ Bm,
             float* __restrict__ Cext, int N, int K) {
    float* C = (DST == 0) ? g_q : (DST == 1) ? g_k : (DST == 2) ? g_v : Cext;
    const float* A = (DST == 3) ? (const float*)g_o : Ain;

    const int BK = 16;
    const int SPLITK = 4;
    int n0   = blockIdx.x * 64;
    int kspan = K / SPLITK;
    int kbeg = blockIdx.y * kspan;
    int kend = kbeg + kspan;

    int tid = threadIdx.x;
    int tx = tid & 15, ty = tid >> 4;

    __shared__ __align__(16) float As[BK][64 + 4];
    __shared__ __align__(16) float Bs[BK][64 + 4];

    float acc[4][4] = {};

    int lm = tid >> 2;           // 0..63 : row within tile
    int lk = (tid & 3) * 4;      // k offset (float4)

    for (int k0 = kbeg; k0 < kend; k0 += BK) {
        float4 a4 = *reinterpret_cast<const float4*>(&A [lm * K + k0 + lk]);
        float4 b4 = *reinterpret_cast<const float4*>(&Bm[(n0 + lm) * K + k0 + lk]);
        As[lk+0][lm] = a4.x; As[lk+1][lm] = a4.y; As[lk+2][lm] = a4.z; As[lk+3][lm] = a4.w;
        Bs[lk+0][lm] = b4.x; Bs[lk+1][lm] = b4.y; Bs[lk+2][lm] = b4.z; Bs[lk+3][lm] = b4.w;
        __syncthreads();
        #pragma unroll
        for (int k = 0; k < BK; ++k) {
            float4 av = *reinterpret_cast<const float4*>(&As[k][ty * 4]);
            float4 bv = *reinterpret_cast<const float4*>(&Bs[k][tx * 4]);
            acc[0][0] += av.x * bv.x; acc[0][1] += av.x * bv.y; acc[0][2] += av.x * bv.z; acc[0][3] += av.x * bv.w;
            acc[1][0] += av.y * bv.x; acc[1][1] += av.y * bv.y; acc[1][2] += av.y * bv.z; acc[1][3] += av.y * bv.w;
            acc[2][0] += av.z * bv.x; acc[2][1] += av.z * bv.y; acc[2][2] += av.z * bv.z; acc[2][3] += av.z * bv.w;
            acc[3][0] += av.w * bv.x; acc[3][1] += av.w * bv.y; acc[3][2] += av.w * bv.z; acc[3][3] += av.w * bv.w;
        }
        __syncthreads();
    }

    #pragma unroll
    for (int i = 0; i < 4; ++i)
        #pragma unroll
        for (int j = 0; j < 4; ++j)
            atomicAdd(&C[(ty * 4 + i) * N + n0 + tx * 4 + j], acc[i][j]);
}

// -------- RMSNorm + RoPE on q and k rows (in place) --------
__global__ __launch_bounds__(256)
void normrope_kernel(const float* __restrict__ qns, const float* __restrict__ kns,
                     const int* __restrict__ kv_lens) {
    int r = blockIdx.x;
    int d = threadIdx.x;

    float* ptr; const float* sc; int b, t;
    if (r < B_*T_*H_) {
        ptr = g_q + (long)r * HD_; sc = qns;
        b = r / (T_ * H_); t = (r / H_) % T_;
    } else {
        int rk = r - B_*T_*H_;
        ptr = g_k + (long)rk * HD_; sc = kns;
        b = rk / (T_ * G_); t = (rk / G_) % T_;
    }

    float v = ptr[d];
    float ss = v * v;
    #pragma unroll
    for (int off = 16; off; off >>= 1) ss += __shfl_xor_sync(0xffffffffu, ss, off);
    __shared__ float red[8];
    if ((d & 31) == 0) red[d >> 5] = ss;
    __syncthreads();
    float tot = 0.f;
    #pragma unroll
    for (int w = 0; w < 8; ++w) tot += red[w];

    float rms = rsqrtf(tot / (float)HD_ + EPS_);
    float y = v * rms * (1.f + sc[d]);

    __shared__ float yb[HD_];
    yb[d] = y;
    __syncthreads();

    if (d < 128) {
        int pos = kv_lens[b] + t;
        // inv = theta^{-d/128} = 2^{-d * log2(1e4)/128}
        float inv = exp2f(-(float)d * (13.287712379549449f / 128.f));
        float ang = (float)pos * inv;
        float sn, cs;
        sincosf(ang, &sn, &cs);   // accurate version: ang can be ~4000 rad
        float x1 = yb[d], x2 = yb[d + 128];
        ptr[d]       = x1 * cs - x2 * sn;
        ptr[d + 128] = x2 * cs + x1 * sn;
    }
}

// -------- split-window flash attention (partials) --------
// grid: (NCHUNK, G_, B_), block 256. Each block serves NQ=8 queries of (b,g),
// streaming a segment of the window once. Warp w owns query w's softmax stats.
__global__ __launch_bounds__(256)
void attn_kernel(const float* __restrict__ k_blocks, const float* __restrict__ v_blocks,
                 const int* __restrict__ block_tables, const int* __restrict__ kv_lens) {
    int c = blockIdx.x, g = blockIdx.y, b = blockIdx.z;
    int tid = threadIdx.x;
    int lane = tid & 31, warp = tid >> 5;

    __shared__ __align__(16) float Qs[NQ][HD_];
    __shared__ __align__(16) float Ks[BLOCK_][HD_];
    __shared__ __align__(16) float Vs[BLOCK_][HD_];
    __shared__ __align__(16) float Ps[BLOCK_][NQ];   // j-major: p for (key j, query q)
    __shared__ float Al[NQ];

    int kvlen = kv_lens[b];
    int lo = max(0, kvlen - (WINDOW_ - 1));
    int hi = kvlen + T_ - 1;
    int L  = hi - lo + 1;
    int clen = (L + NCHUNK - 1) / NCHUNK;
    int cbeg = lo + c * clen;
    int cend = min(cbeg + clen, hi + 1);

    // load all 8 query vectors
    for (int e = tid; e < NQ * HD_; e += 256) {
        int qi = e >> 8, d = e & 255;
        int hl = qi >> 2, t = qi & 3;
        Qs[qi][d] = g_q[(((b * T_ + t) * H_) + g * GSZ_ + hl) * HD_ + d];
    }

    float acc[NQ];
    #pragma unroll
    for (int i = 0; i < NQ; ++i) acc[i] = 0.f;

    int qi_w  = warp;                 // warp owns this query's stats
    int t_w   = qi_w & 3;
    int pos_w = kvlen + t_w;
    float m_run = -INFINITY, l_run = 0.f;

    __syncthreads();

    for (int tbeg = cbeg; tbeg < cend; tbeg += BLOCK_) {
        int tn = min(BLOCK_, cend - tbeg);

        // cooperative K/V tile load (16 rows x 256 floats each)
        #pragma unroll
        for (int i = 0; i < 4; ++i) {
            int j  = (tid >> 6) + i * 4;   // 0..15
            int d4 = (tid & 63);           // float4 index
            int jp = tbeg + j;
            float4 kv4 = make_float4(0.f, 0.f, 0.f, 0.f), vv4 = kv4;
            if (j < tn) {
                const float *kp, *vp;
                if (jp >= kvlen) {
                    int t = min(jp - kvlen, T_ - 1);
                    kp = &g_k[((b * T_ + t) * G_ + g) * HD_];
                    vp = &g_v[((b * T_ + t) * G_ + g) * HD_];
                } else {
                    int blk = block_tables[b * NBLK_ + (jp >> 4)];
                    long off = (((long)blk * G_ + g) * BLOCK_ + (jp & 15)) * (long)HD_;
                    kp = k_blocks + off;
                    vp = v_blocks + off;
                }
                kv4 = reinterpret_cast<const float4*>(kp)[d4];
                vv4 = reinterpret_cast<const float4*>(vp)[d4];
            }
            reinterpret_cast<float4*>(&Ks[j][0])[d4] = kv4;
            reinterpret_cast<float4*>(&Vs[j][0])[d4] = vv4;
        }
        __syncthreads();

        // scores for this warp's query
        float sreg[BLOCK_];
        #pragma unroll
        for (int j = 0; j < BLOCK_; ++j) {
            const float4* q4 = reinterpret_cast<const float4*>(&Qs[qi_w][0]);
            const float4* k4 = reinterpret_cast<const float4*>(&Ks[j][0]);
            float a = 0.f;
            #pragma unroll
            for (int i = 0; i < 2; ++i) {
                float4 qa = q4[lane * 2 + i], kb = k4[lane * 2 + i];
                a += qa.x * kb.x + qa.y * kb.y + qa.z * kb.z + qa.w * kb.w;
            }
            #pragma unroll
            for (int off = 16; off; off >>= 1) a += __shfl_xor_sync(0xffffffffu, a, off);
            int jp = tbeg + j;
            bool valid = (j < tn) && (jp <= pos_w) && (jp > pos_w - WINDOW_);
            sreg[j] = valid ? a * SCALE_ : -INFINITY;
        }

        float tmax = -INFINITY;
        #pragma unroll
        for (int j = 0; j < BLOCK_; ++j) tmax = fmaxf(tmax, sreg[j]);

        float alpha;
        if (tmax == -INFINITY) {           // whole tile masked for this query
            alpha = 1.f;
            if (lane < BLOCK_) Ps[lane][qi_w] = 0.f;
        } else {
            float m_new = fmaxf(m_run, tmax);
            alpha = __expf(m_run - m_new); // m_run=-inf -> 0
            float psum = 0.f;
            #pragma unroll
            for (int j = 0; j < BLOCK_; ++j) psum += __expf(sreg[j] - m_new);
            l_run = l_run * alpha + psum;
            m_run = m_new;
            if (lane < BLOCK_) Ps[lane][qi_w] = __expf(sreg[lane] - m_new);
        }
        if (lane == 0) Al[qi_w] = alpha;
        __syncthreads();

        // accumulate P*V: thread owns dim d = tid for all 8 queries
        {
            int d = tid;
            #pragma unroll
            for (int q = 0; q < NQ; ++q) acc[q] *= Al[q];
            #pragma unroll
            for (int j = 0; j < BLOCK_; ++j) {
                float v = Vs[j][d];
                float4 p0 = *reinterpret_cast<const float4*>(&Ps[j][0]);
                float4 p1 = *reinterpret_cast<const float4*>(&Ps[j][4]);
                acc[0] += p0.x * v; acc[1] += p0.y * v; acc[2] += p0.z * v; acc[3] += p0.w * v;
                acc[4] += p1.x * v; acc[5] += p1.y * v; acc[6] += p1.z * v; acc[7] += p1.w * v;
            }
        }
        __syncthreads();
    }

    // write partials
    int base = ((b * G_ + g) * NCHUNK + c) * NQ;
    if (lane == 0) { g_pm[base + qi_w] = m_run; g_pl[base + qi_w] = l_run; }
    #pragma unroll
    for (int q = 0; q < NQ; ++q)
        g_po[(long)(base + q) * HD_ + tid] = acc[q];
}

// -------- combine split-window partials -> g_o --------
__global__ __launch_bounds__(256)
void combine_kernel() {
    int bg = blockIdx.x;
    int b = bg / G_, g = bg % G_;
    int d = threadIdx.x;
    int base = (b * G_ + g) * NCHUNK * NQ;

    for (int q = 0; q < NQ; ++q) {
        float mc[NCHUNK], lc[NCHUNK];
        float M = -INFINITY;
        #pragma unroll
        for (int c = 0; c < NCHUNK; ++c) {
            mc[c] = g_pm[base + c * NQ + q];
            lc[c] = g_pl[base + c * NQ + q];
            M = fmaxf(M, mc[c]);
        }
        float Lsum = 0.f, o = 0.f;
        #pragma unroll
        for (int c = 0; c < NCHUNK; ++c) {
            float w = __expf(mc[c] - M);   // mc=-inf -> 0
            Lsum += lc[c] * w;
            o += g_po[(long)(base + c * NQ + q) * HD_ + d] * w;
        }
        int hl = q >> 2, t = q & 3;
        g_o[((b * T_ + t) * H_ + g * GSZ_ + hl) * HD_ + d] = o / Lsum;
    }
}

// -------- launcher --------
extern "C" void kernel_launch(void* const* d_in, const int* in_sizes, int n_in,
                              void* d_out, int out_size) {
    const float* x   = (const float*)d_in[0];
    const float* Wq  = (const float*)d_in[1];
    const float* Wk  = (const float*)d_in[2];
    const float* Wv  = (const float*)d_in[3];
    const float* Wo  = (const float*)d_in[4];
    const float* qns = (const float*)d_in[5];
    const float* kns = (const float*)d_in[6];
    const float* kb  = (const float*)d_in[7];
    const float* vb  = (const float*)d_in[8];
    const int*   bt  = (const int*)d_in[9];
    const int*   kvl = (const int*)d_in[10];
    float* out = (float*)d_out;

    zero_kernel<<<512, 256>>>(out);

    gemm_nt<0><<<dim3((H_*HD_) / 64, 4), 256>>>(x, Wq, nullptr, H_*HD_, D_);
    gemm_nt<1><<<dim3((G_*HD_) / 64, 4), 256>>>(x, Wk, nullptr, G_*HD_, D_);
    gemm_nt<2><<<dim3((G_*HD_) / 64, 4), 256>>>(x, Wv, nullptr, G_*HD_, D_);

    normrope_kernel<<<B_*T_*(H_ + G_), 256>>>(qns, kns, kvl);

    attn_kernel<<<dim3(NCHUNK, G_, B_), 256>>>(kb, vb, bt, kvl);
    combine_kernel<<<B_*G_, 256>>>();

    // NOTE: A operand (g_o) is resolved inside the kernel via DST=3;
    // the first pointer argument is ignored there.
    gemm_nt<3><<<dim3(D_ / 64, 4), 256>>>(nullptr, Wo, out, D_, H_*HD_);
}

// round 5
// speedup vs baseline: 1.4997x; 1.4997x over previous
#include <cuda_runtime.h>
#include <cuda_bf16.h>
#include <math.h>

// Problem constants
#define B_      16
#define T_      4
#define D_      2048
#define H_      8
#define G_      4
#define GSZ_    2
#define HD_     256
#define BLOCK_  16
#define WINDOW_ 1024
#define NBLK_   257
#define NCHUNK  8
#define NQ      8            // GSZ_ * T_ queries per (b,g)
#define SCALE_  0.0625f      // 256^-0.5
#define EPS_    1e-6f

// -------- device scratch (no allocs allowed) --------
__device__ __align__(16) float g_q [B_*T_*H_*HD_];          // 131072
__device__ __align__(16) float g_k [B_*T_*G_*HD_];          // 65536
__device__ __align__(16) float g_v [B_*T_*G_*HD_];          // 65536
__device__ __align__(16) float g_o [B_*T_*H_*HD_];          // 131072
__device__ __align__(16) float g_po[B_*G_*NCHUNK*NQ*HD_];   // 1M floats
__device__ __align__(16) float g_pm[B_*G_*NCHUNK*NQ];
__device__ __align__(16) float g_pl[B_*G_*NCHUNK*NQ];

// -------- zero scratch + output (atomic accumulation targets) --------
__global__ void zero_kernel(float* __restrict__ out) {
    int i = blockIdx.x * 256 + threadIdx.x;   // grid 512 -> i < 131072
    if (i < B_*T_*H_*HD_) g_q[i] = 0.f;
    if (i < B_*T_*G_*HD_) { g_k[i] = 0.f; g_v[i] = 0.f; }
    if (i < B_*T_*D_)     out[i] = 0.f;
}

// ==================== fused QKV GEMM ====================
// C[64, Nv] += x[64,2048] * W[Nv,2048]^T for W in {Wq,Wk,Wv} (virtual N=4096).
// grid: (64 n-tiles, SPLITK=8). 256 threads, BN=64, BK=16, 4x4 microtile,
// register double-buffered global->smem pipeline, atomicAdd epilogue.
__global__ __launch_bounds__(256)
void gemm_qkv(const float* __restrict__ x,
              const float* __restrict__ Wq,
              const float* __restrict__ Wk,
              const float* __restrict__ Wv) {
    const int K = D_;
    const int BK = 16;
    const int SPLITK = 8;

    int n0 = blockIdx.x * 64;          // virtual n in [0,4096)
    const float* Bm; float* C; int Nc; int nb;
    if (n0 < 2048)      { Bm = Wq + (long)n0 * K;          C = g_q; Nc = 2048; nb = n0; }
    else if (n0 < 3072) { Bm = Wk + (long)(n0 - 2048) * K; C = g_k; Nc = 1024; nb = n0 - 2048; }
    else                { Bm = Wv + (long)(n0 - 3072) * K; C = g_v; Nc = 1024; nb = n0 - 3072; }

    int kspan = K / SPLITK;            // 256
    int kbeg = blockIdx.y * kspan;
    int kend = kbeg + kspan;

    int tid = threadIdx.x;
    int tx = tid & 15, ty = tid >> 4;
    int lm = tid >> 2;                 // row 0..63
    int lk = (tid & 3) * 4;            // k offset

    __shared__ __align__(16) float As[BK][64 + 4];
    __shared__ __align__(16) float Bs[BK][64 + 4];

    const float* Ap = x  + (long)lm * K + lk;
    const float* Bp = Bm + (long)lm * K + lk;

    float acc[4][4] = {};

    float4 a4 = *reinterpret_cast<const float4*>(Ap + kbeg);
    float4 b4 = *reinterpret_cast<const float4*>(Bp + kbeg);

    for (int k0 = kbeg; k0 < kend; k0 += BK) {
        As[lk+0][lm] = a4.x; As[lk+1][lm] = a4.y; As[lk+2][lm] = a4.z; As[lk+3][lm] = a4.w;
        Bs[lk+0][lm] = b4.x; Bs[lk+1][lm] = b4.y; Bs[lk+2][lm] = b4.z; Bs[lk+3][lm] = b4.w;
        __syncthreads();
        if (k0 + BK < kend) {          // prefetch next tile while computing
            a4 = *reinterpret_cast<const float4*>(Ap + k0 + BK);
            b4 = *reinterpret_cast<const float4*>(Bp + k0 + BK);
        }
        #pragma unroll
        for (int k = 0; k < BK; ++k) {
            float4 av = *reinterpret_cast<const float4*>(&As[k][ty * 4]);
            float4 bv = *reinterpret_cast<const float4*>(&Bs[k][tx * 4]);
            acc[0][0] += av.x * bv.x; acc[0][1] += av.x * bv.y; acc[0][2] += av.x * bv.z; acc[0][3] += av.x * bv.w;
            acc[1][0] += av.y * bv.x; acc[1][1] += av.y * bv.y; acc[1][2] += av.y * bv.z; acc[1][3] += av.y * bv.w;
            acc[2][0] += av.z * bv.x; acc[2][1] += av.z * bv.y; acc[2][2] += av.z * bv.z; acc[2][3] += av.z * bv.w;
            acc[3][0] += av.w * bv.x; acc[3][1] += av.w * bv.y; acc[3][2] += av.w * bv.z; acc[3][3] += av.w * bv.w;
        }
        __syncthreads();
    }

    #pragma unroll
    for (int i = 0; i < 4; ++i)
        #pragma unroll
        for (int j = 0; j < 4; ++j)
            atomicAdd(&C[(long)(ty * 4 + i) * Nc + nb + tx * 4 + j], acc[i][j]);
}

// ==================== Wo GEMM: out[64,2048] += g_o[64,2048] * Wo[2048,2048]^T
__global__ __launch_bounds__(256)
void gemm_wo(const float* __restrict__ Wm, float* __restrict__ C) {
    const int K = H_ * HD_;            // 2048
    const int N = D_;                  // 2048
    const int BK = 16;
    const int SPLITK = 8;

    int n0 = blockIdx.x * 64;
    int kspan = K / SPLITK;
    int kbeg = blockIdx.y * kspan;
    int kend = kbeg + kspan;

    int tid = threadIdx.x;
    int tx = tid & 15, ty = tid >> 4;
    int lm = tid >> 2;
    int lk = (tid & 3) * 4;

    __shared__ __align__(16) float As[BK][64 + 4];
    __shared__ __align__(16) float Bs[BK][64 + 4];

    const float* Ap = g_o + (long)lm * K + lk;
    const float* Bp = Wm + (long)(n0 + lm) * K + lk;

    float acc[4][4] = {};

    float4 a4 = *reinterpret_cast<const float4*>(Ap + kbeg);
    float4 b4 = *reinterpret_cast<const float4*>(Bp + kbeg);

    for (int k0 = kbeg; k0 < kend; k0 += BK) {
        As[lk+0][lm] = a4.x; As[lk+1][lm] = a4.y; As[lk+2][lm] = a4.z; As[lk+3][lm] = a4.w;
        Bs[lk+0][lm] = b4.x; Bs[lk+1][lm] = b4.y; Bs[lk+2][lm] = b4.z; Bs[lk+3][lm] = b4.w;
        __syncthreads();
        if (k0 + BK < kend) {
            a4 = *reinterpret_cast<const float4*>(Ap + k0 + BK);
            b4 = *reinterpret_cast<const float4*>(Bp + k0 + BK);
        }
        #pragma unroll
        for (int k = 0; k < BK; ++k) {
            float4 av = *reinterpret_cast<const float4*>(&As[k][ty * 4]);
            float4 bv = *reinterpret_cast<const float4*>(&Bs[k][tx * 4]);
            acc[0][0] += av.x * bv.x; acc[0][1] += av.x * bv.y; acc[0][2] += av.x * bv.z; acc[0][3] += av.x * bv.w;
            acc[1][0] += av.y * bv.x; acc[1][1] += av.y * bv.y; acc[1][2] += av.y * bv.z; acc[1][3] += av.y * bv.w;
            acc[2][0] += av.z * bv.x; acc[2][1] += av.z * bv.y; acc[2][2] += av.z * bv.z; acc[2][3] += av.z * bv.w;
            acc[3][0] += av.w * bv.x; acc[3][1] += av.w * bv.y; acc[3][2] += av.w * bv.z; acc[3][3] += av.w * bv.w;
        }
        __syncthreads();
    }

    #pragma unroll
    for (int i = 0; i < 4; ++i)
        #pragma unroll
        for (int j = 0; j < 4; ++j)
            atomicAdd(&C[(long)(ty * 4 + i) * N + n0 + tx * 4 + j], acc[i][j]);
}

// -------- RMSNorm + RoPE on q and k rows (in place) --------
__global__ __launch_bounds__(256)
void normrope_kernel(const float* __restrict__ qns, const float* __restrict__ kns,
                     const int* __restrict__ kv_lens) {
    int r = blockIdx.x;
    int d = threadIdx.x;

    float* ptr; const float* sc; int b, t;
    if (r < B_*T_*H_) {
        ptr = g_q + (long)r * HD_; sc = qns;
        b = r / (T_ * H_); t = (r / H_) % T_;
    } else {
        int rk = r - B_*T_*H_;
        ptr = g_k + (long)rk * HD_; sc = kns;
        b = rk / (T_ * G_); t = (rk / G_) % T_;
    }

    float v = ptr[d];
    float ss = v * v;
    #pragma unroll
    for (int off = 16; off; off >>= 1) ss += __shfl_xor_sync(0xffffffffu, ss, off);
    __shared__ float red[8];
    if ((d & 31) == 0) red[d >> 5] = ss;
    __syncthreads();
    float tot = 0.f;
    #pragma unroll
    for (int w = 0; w < 8; ++w) tot += red[w];

    float rms = rsqrtf(tot / (float)HD_ + EPS_);
    float y = v * rms * (1.f + sc[d]);

    __shared__ float yb[HD_];
    yb[d] = y;
    __syncthreads();

    if (d < 128) {
        int pos = kv_lens[b] + t;
        float inv = exp2f(-(float)d * (13.287712379549449f / 128.f));
        float ang = (float)pos * inv;
        float sn, cs;
        sincosf(ang, &sn, &cs);
        float x1 = yb[d], x2 = yb[d + 128];
        ptr[d]       = x1 * cs - x2 * sn;
        ptr[d + 128] = x2 * cs + x1 * sn;
    }
}

// -------- split-window flash attention (partials) --------
// grid: (NCHUNK, G_, B_) = 512 blocks, 256 threads. Each block serves NQ=8
// queries of (b,g) over its key segment. K/V tiles prefetched into registers
// so loads overlap score/softmax/PV compute.
__global__ __launch_bounds__(256)
void attn_kernel(const float* __restrict__ k_blocks, const float* __restrict__ v_blocks,
                 const int* __restrict__ block_tables, const int* __restrict__ kv_lens) {
    int c = blockIdx.x, g = blockIdx.y, b = blockIdx.z;
    int tid = threadIdx.x;
    int lane = tid & 31, warp = tid >> 5;

    __shared__ __align__(16) float Qs[NQ][HD_];
    __shared__ __align__(16) float Ks[BLOCK_][HD_];
    __shared__ __align__(16) float Vs[BLOCK_][HD_];
    __shared__ __align__(16) float Ps[BLOCK_][NQ];
    __shared__ float Al[NQ];

    int kvlen = kv_lens[b];
    int lo = max(0, kvlen - (WINDOW_ - 1));
    int hi = kvlen + T_ - 1;
    int L  = hi - lo + 1;
    int clen = (L + NCHUNK - 1) / NCHUNK;
    int cbeg = lo + c * clen;
    int cend = min(cbeg + clen, hi + 1);

    // load all 8 query vectors
    for (int e = tid; e < NQ * HD_; e += 256) {
        int qi = e >> 8, d = e & 255;
        int hl = qi >> 2, t = qi & 3;
        Qs[qi][d] = g_q[(((b * T_ + t) * H_) + g * GSZ_ + hl) * HD_ + d];
    }

    float acc[NQ];
    #pragma unroll
    for (int i = 0; i < NQ; ++i) acc[i] = 0.f;

    int qi_w  = warp;
    int t_w   = qi_w & 3;
    int pos_w = kvlen + t_w;
    float m_run = -INFINITY, l_run = 0.f;

    int jrow = tid >> 6;        // loader: base row 0..3
    int d4   = tid & 63;        // float4 index within row

    // prefetch registers for one K/V tile (4 rows per thread)
    float4 kreg[4], vreg[4];

    auto load_tile = [&](int tbeg, int tn) {
        #pragma unroll
        for (int i = 0; i < 4; ++i) {
            int j  = jrow + i * 4;
            int jp = tbeg + j;
            float4 kz = make_float4(0.f,0.f,0.f,0.f), vz = kz;
            if (j < tn) {
                const float *kp, *vp;
                if (jp >= kvlen) {
                    int t = min(jp - kvlen, T_ - 1);
                    kp = &g_k[((b * T_ + t) * G_ + g) * HD_];
                    vp = &g_v[((b * T_ + t) * G_ + g) * HD_];
                } else {
                    int blk = block_tables[b * NBLK_ + (jp >> 4)];
                    long off = (((long)blk * G_ + g) * BLOCK_ + (jp & 15)) * (long)HD_;
                    kp = k_blocks + off;
                    vp = v_blocks + off;
                }
                kz = reinterpret_cast<const float4*>(kp)[d4];
                vz = reinterpret_cast<const float4*>(vp)[d4];
            }
            kreg[i] = kz; vreg[i] = vz;
        }
    };

    __syncthreads();   // Qs ready

    if (cbeg < cend) load_tile(cbeg, min(BLOCK_, cend - cbeg));

    for (int tbeg = cbeg; tbeg < cend; tbeg += BLOCK_) {
        int tn = min(BLOCK_, cend - tbeg);

        // commit prefetched tile to smem
        #pragma unroll
        for (int i = 0; i < 4; ++i) {
            int j = jrow + i * 4;
            reinterpret_cast<float4*>(&Ks[j][0])[d4] = kreg[i];
            reinterpret_cast<float4*>(&Vs[j][0])[d4] = vreg[i];
        }
        __syncthreads();

        // issue next tile's loads (overlap with compute below)
        int nbeg = tbeg + BLOCK_;
        if (nbeg < cend) load_tile(nbeg, min(BLOCK_, cend - nbeg));

        // scores for this warp's query
        float sreg[BLOCK_];
        #pragma unroll
        for (int j = 0; j < BLOCK_; ++j) {
            const float4* q4 = reinterpret_cast<const float4*>(&Qs[qi_w][0]);
            const float4* k4 = reinterpret_cast<const float4*>(&Ks[j][0]);
            float a = 0.f;
            #pragma unroll
            for (int i = 0; i < 2; ++i) {
                float4 qa = q4[lane * 2 + i], kb = k4[lane * 2 + i];
                a += qa.x * kb.x + qa.y * kb.y + qa.z * kb.z + qa.w * kb.w;
            }
            #pragma unroll
            for (int off = 16; off; off >>= 1) a += __shfl_xor_sync(0xffffffffu, a, off);
            int jp = tbeg + j;
            bool valid = (j < tn) && (jp <= pos_w) && (jp > pos_w - WINDOW_);
            sreg[j] = valid ? a * SCALE_ : -INFINITY;
        }

        float tmax = -INFINITY;
        #pragma unroll
        for (int j = 0; j < BLOCK_; ++j) tmax = fmaxf(tmax, sreg[j]);

        float alpha;
        if (tmax == -INFINITY) {
            alpha = 1.f;
            if (lane < BLOCK_) Ps[lane][qi_w] = 0.f;
        } else {
            float m_new = fmaxf(m_run, tmax);
            alpha = __expf(m_run - m_new);
            float psum = 0.f;
            #pragma unroll
            for (int j = 0; j < BLOCK_; ++j) psum += __expf(sreg[j] - m_new);
            l_run = l_run * alpha + psum;
            m_run = m_new;
            if (lane < BLOCK_) Ps[lane][qi_w] = __expf(sreg[lane] - m_new);
        }
        if (lane == 0) Al[qi_w] = alpha;
        __syncthreads();

        // accumulate P*V: thread owns dim d = tid for all 8 queries
        {
            int d = tid;
            #pragma unroll
            for (int q = 0; q < NQ; ++q) acc[q] *= Al[q];
            #pragma unroll
            for (int j = 0; j < BLOCK_; ++j) {
                float v = Vs[j][d];
                float4 p0 = *reinterpret_cast<const float4*>(&Ps[j][0]);
                float4 p1 = *reinterpret_cast<const float4*>(&Ps[j][4]);
                acc[0] += p0.x * v; acc[1] += p0.y * v; acc[2] += p0.z * v; acc[3] += p0.w * v;
                acc[4] += p1.x * v; acc[5] += p1.y * v; acc[6] += p1.z * v; acc[7] += p1.w * v;
            }
        }
        __syncthreads();
    }

    // write partials
    int base = ((b * G_ + g) * NCHUNK + c) * NQ;
    if (lane == 0) { g_pm[base + qi_w] = m_run; g_pl[base + qi_w] = l_run; }
    #pragma unroll
    for (int q = 0; q < NQ; ++q)
        g_po[(long)(base + q) * HD_ + tid] = acc[q];
}

// -------- combine split-window partials -> g_o --------
__global__ __launch_bounds__(256)
void combine_kernel() {
    int bg = blockIdx.x;
    int b = bg / G_, g = bg % G_;
    int d = threadIdx.x;
    int base = (b * G_ + g) * NCHUNK * NQ;

    for (int q = 0; q < NQ; ++q) {
        float mc[NCHUNK], lc[NCHUNK];
        float M = -INFINITY;
        #pragma unroll
        for (int c = 0; c < NCHUNK; ++c) {
            mc[c] = g_pm[base + c * NQ + q];
            lc[c] = g_pl[base + c * NQ + q];
            M = fmaxf(M, mc[c]);
        }
        float Lsum = 0.f, o = 0.f;
        #pragma unroll
        for (int c = 0; c < NCHUNK; ++c) {
            float w = __expf(mc[c] - M);
            Lsum += lc[c] * w;
            o += g_po[(long)(base + c * NQ + q) * HD_ + d] * w;
        }
        int hl = q >> 2, t = q & 3;
        g_o[((b * T_ + t) * H_ + g * GSZ_ + hl) * HD_ + d] = o / Lsum;
    }
}

// -------- launcher --------
extern "C" void kernel_launch(void* const* d_in, const int* in_sizes, int n_in,
                              void* d_out, int out_size) {
    const float* x   = (const float*)d_in[0];
    const float* Wq  = (const float*)d_in[1];
    const float* Wk  = (const float*)d_in[2];
    const float* Wv  = (const float*)d_in[3];
    const float* Wo  = (const float*)d_in[4];
    const float* qns = (const float*)d_in[5];
    const float* kns = (const float*)d_in[6];
    const float* kb  = (const float*)d_in[7];
    const float* vb  = (const float*)d_in[8];
    const int*   bt  = (const int*)d_in[9];
    const int*   kvl = (const int*)d_in[10];
    float* out = (float*)d_out;

    zero_kernel<<<512, 256>>>(out);

    gemm_qkv<<<dim3(64, 8), 256>>>(x, Wq, Wk, Wv);      // 512 CTAs

    normrope_kernel<<<B_*T_*(H_ + G_), 256>>>(qns, kns, kvl);

    attn_kernel<<<dim3(NCHUNK, G_, B_), 256>>>(kb, vb, bt, kvl);   // 512 CTAs
    combine_kernel<<<B_*G_, 256>>>();

    gemm_wo<<<dim3(32, 8), 256>>>(Wo, out);             // 256 CTAs
}